// round 5
// baseline (speedup 1.0000x reference)
#include <cuda_runtime.h>

// Problem constants (fixed by the reference):
//   S=3 symmetries, B=512 batches, N=1000 points, G=32 (G^3=32768 voxels)
//   GRID_MIN = -0.5 + 0.5/32 = -0.484375, scale = GRID/(2*GBOUND) = 32
#define S_SYM   3
#define B_BATCH 512
#define N_PTS   1000
#define G3      32768
#define SB_TOT  (S_SYM * B_BATCH)
#define GRID_MIN_F (-0.484375f)
#define NTHREADS 512
#define NWARPS   (NTHREADS / 32)

// Per-batch partial sums: [0..511]=plane, [512..1023]=quat. Plus ticket.
__device__ float g_partial[2 * B_BATCH];
__device__ unsigned int g_count;   // zero-initialized; reset by last block

__device__ __forceinline__ float fast_sqrt(float x) {
    float r;
    asm("sqrt.approx.f32 %0, %1;" : "=f"(r) : "f"(x));
    return r;
}
__device__ __forceinline__ float fast_rcp(float x) {
    float r;
    asm("rcp.approx.f32 %0, %1;" : "=f"(r) : "f"(x));
    return r;
}

__device__ __forceinline__ int voxel_lin(float px, float py, float pz) {
    float vx = fminf(fmaxf((px - GRID_MIN_F) * 32.0f, 0.0f), 31.0f);
    float vy = fminf(fmaxf((py - GRID_MIN_F) * 32.0f, 0.0f), 31.0f);
    float vz = fminf(fmaxf((pz - GRID_MIN_F) * 32.0f, 0.0f), 31.0f);
    // __float2int_rn == round-half-even == jnp.round after clip
    return __float2int_rn(vx) * 1024 + __float2int_rn(vy) * 32 + __float2int_rn(vz);
}

__global__ __launch_bounds__(NTHREADS, 2)   // cap 64 regs -> deep MLP allowed
void sym_loss_kernel(const float* __restrict__ planes,
                     const float* __restrict__ quats,
                     const float* __restrict__ cps,
                     const float* __restrict__ pts,
                     const float* __restrict__ vol,
                     float* __restrict__ out)
{
    __shared__ float4 s_pts[N_PTS];           // padded to 16B for LDS.128
    __shared__ float s_red[2 * NWARPS];
    __shared__ int   s_is_last;

    const int b = blockIdx.x;                 // one block per batch
    const float* cpb = cps + (size_t)b * (3 * G3);
    const float* vb  = vol + (size_t)b * G3;
    const float* pb  = pts + (size_t)b * (3 * N_PTS);

    // Stage the batch's points once (shared across all 3 symmetries).
    for (int i = threadIdx.x; i < N_PTS; i += NTHREADS)
        s_pts[i] = make_float4(pb[3 * i + 0], pb[3 * i + 1], pb[3 * i + 2], 0.0f);
    __syncthreads();

    // Hoist all symmetry params into registers.
    float plx[S_SYM], ply[S_SYM], plz[S_SYM], plw[S_SYM], inv[S_SYM];
    float qw[S_SYM], qx[S_SYM], qy[S_SYM], qz[S_SYM];
    #pragma unroll
    for (int s = 0; s < S_SYM; s++) {
        float4 pl = reinterpret_cast<const float4*>(planes)[s * B_BATCH + b];
        float4 qq = reinterpret_cast<const float4*>(quats)[s * B_BATCH + b];
        plx[s] = pl.x; ply[s] = pl.y; plz[s] = pl.z; plw[s] = pl.w;
        inv[s] = fast_rcp(pl.x * pl.x + pl.y * pl.y + pl.z * pl.z + 1e-8f);
        qw[s] = qq.x; qx[s] = qq.y; qy[s] = qq.z; qz[s] = qq.w;
    }

    float lp = 0.0f, lq = 0.0f;

    // Point-major: one point -> all 6 transforms -> 24 batched gathers.
    for (int n = threadIdx.x; n < N_PTS; n += NTHREADS) {
        float4 p = s_pts[n];
        const float px = p.x, py = p.y, pz = p.z;

        float tx[6], ty[6], tz[6];
        int lin[6];
        #pragma unroll
        for (int s = 0; s < S_SYM; s++) {
            // plane reflection
            float t = 2.0f * (px * plx[s] + py * ply[s] + pz * plz[s] + plw[s]) * inv[s];
            tx[2 * s] = px - t * plx[s];
            ty[2 * s] = py - t * ply[s];
            tz[2 * s] = pz - t * plz[s];
            lin[2 * s] = voxel_lin(tx[2 * s], ty[2 * s], tz[2 * s]);
            // quat rotation
            float tw = -qx[s] * px - qy[s] * py - qz[s] * pz;
            float ax =  qw[s] * px + qy[s] * pz - qz[s] * py;
            float ay =  qw[s] * py - qx[s] * pz + qz[s] * px;
            float az =  qw[s] * pz + qx[s] * py - qy[s] * px;
            tx[2 * s + 1] = -tw * qx[s] + ax * qw[s] - ay * qz[s] + az * qy[s];
            ty[2 * s + 1] = -tw * qy[s] + ax * qz[s] + ay * qw[s] - az * qx[s];
            tz[2 * s + 1] = -tw * qz[s] - ax * qy[s] + ay * qx[s] + az * qw[s];
            lin[2 * s + 1] = voxel_lin(tx[2 * s + 1], ty[2 * s + 1], tz[2 * s + 1]);
        }

        // Batch all 24 gathers (6 voxel entries x {vol, cp0, cp1, cp2}).
        float vm[6], c0[6], c1[6], c2[6];
        #pragma unroll
        for (int j = 0; j < 6; j++) {
            vm[j] = __ldg(vb + lin[j]);
            const float* c = cpb + 3 * lin[j];
            c0[j] = __ldg(c + 0);
            c1[j] = __ldg(c + 1);
            c2[j] = __ldg(c + 2);
        }

        #pragma unroll
        for (int j = 0; j < 6; j++) {
            float m  = 1.0f - vm[j];
            float dx = (tx[j] - c0[j]) * m;
            float dy = (ty[j] - c1[j]) * m;
            float dz = (tz[j] - c2[j]) * m;
            float r  = fast_sqrt(fmaxf(dx * dx + dy * dy + dz * dz, 1e-30f));
            if (j & 1) lq += r; else lp += r;
        }
    }

    // Deterministic block reduction: warp shuffle then fixed-order smem sum.
    #pragma unroll
    for (int off = 16; off > 0; off >>= 1) {
        lp += __shfl_down_sync(0xffffffffu, lp, off);
        lq += __shfl_down_sync(0xffffffffu, lq, off);
    }
    const int lane = threadIdx.x & 31;
    const int wid  = threadIdx.x >> 5;
    if (lane == 0) { s_red[wid] = lp; s_red[NWARPS + wid] = lq; }
    __syncthreads();
    if (threadIdx.x == 0) {
        float a = 0.0f, c2s = 0.0f;
        #pragma unroll
        for (int i = 0; i < NWARPS; i++) { a += s_red[i]; c2s += s_red[NWARPS + i]; }
        g_partial[b] = a;
        g_partial[B_BATCH + b] = c2s;
        __threadfence();
        unsigned t = atomicAdd(&g_count, 1u);
        s_is_last = (t == B_BATCH - 1);
    }
    __syncthreads();

    // Last block performs the final reduction in a FIXED order (deterministic
    // regardless of which block finishes last).
    if (s_is_last) {
        float a = 0.0f, c2s = 0.0f;
        for (int i = threadIdx.x; i < B_BATCH; i += NTHREADS) {
            a   += g_partial[i];
            c2s += g_partial[B_BATCH + i];
        }
        #pragma unroll
        for (int off = 16; off > 0; off >>= 1) {
            a   += __shfl_down_sync(0xffffffffu, a,   off);
            c2s += __shfl_down_sync(0xffffffffu, c2s, off);
        }
        if (lane == 0) { s_red[wid] = a; s_red[NWARPS + wid] = c2s; }
        __syncthreads();
        if (threadIdx.x == 0) {
            float sa = 0.0f, sc = 0.0f;
            #pragma unroll
            for (int i = 0; i < NWARPS; i++) { sa += s_red[i]; sc += s_red[NWARPS + i]; }
            out[0] = sa * (1.0f / (float)SB_TOT);
            out[1] = sc * (1.0f / (float)SB_TOT);
            g_count = 0;   // reset for next graph replay
        }
    }
}

extern "C" void kernel_launch(void* const* d_in, const int* in_sizes, int n_in,
                              void* d_out, int out_size)
{
    const float* planes = (const float*)d_in[0];  // (3,512,4)
    const float* quats  = (const float*)d_in[1];  // (3,512,4)
    const float* cps    = (const float*)d_in[2];  // (512, 32768*3)
    const float* pts    = (const float*)d_in[3];  // (512,1000,3)
    const float* vol    = (const float*)d_in[4];  // (512,1,32,32,32)
    float* out = (float*)d_out;                   // [lp_mean, lq_mean]

    sym_loss_kernel<<<B_BATCH, NTHREADS>>>(planes, quats, cps, pts, vol, out);
}

// round 6
// speedup vs baseline: 1.0863x; 1.0863x over previous
#include <cuda_runtime.h>

// Problem constants (fixed by the reference):
//   S=3 symmetries, B=512 batches, N=1000 points, G=32 (G^3=32768 voxels)
//   GRID_MIN = -0.5 + 0.5/32 = -0.484375, scale = GRID/(2*GBOUND) = 32
#define S_SYM   3
#define B_BATCH 512
#define N_PTS   1000
#define G3      32768
#define SB_TOT  (S_SYM * B_BATCH)
#define GRID_MIN_F (-0.484375f)
#define NTHREADS 512
#define NWARPS   (NTHREADS / 32)

// Per-batch partial sums: [0..511]=plane, [512..1023]=quat. Plus ticket.
__device__ float g_partial[2 * B_BATCH];
__device__ unsigned int g_count;   // zero-initialized; reset by last block

__device__ __forceinline__ float fast_sqrt(float x) {
    float r;
    asm("sqrt.approx.f32 %0, %1;" : "=f"(r) : "f"(x));
    return r;
}
__device__ __forceinline__ float fast_rcp(float x) {
    float r;
    asm("rcp.approx.f32 %0, %1;" : "=f"(r) : "f"(x));
    return r;
}

__global__ __launch_bounds__(NTHREADS, 2)
void sym_loss_kernel(const float* __restrict__ planes,
                     const float* __restrict__ quats,
                     const float* __restrict__ cps,
                     const float* __restrict__ pts,
                     const float* __restrict__ vol,
                     float* __restrict__ out)
{
    __shared__ float4 s_pts[N_PTS];            // padded to 16B for LDS.128
    __shared__ float4 s_corner[8];             // {cp0,cp1,cp2,vol} of 8 grid corners
    __shared__ float  s_red[2 * NWARPS];
    __shared__ int    s_is_last;

    const int b = blockIdx.x;                  // one block per batch
    const float* cpb = cps + (size_t)b * (3 * G3);
    const float* vb  = vol + (size_t)b * G3;
    const float* pb  = pts + (size_t)b * (3 * N_PTS);

    // Stage the 8 corner voxels (k bits = (x,y,z) clamped-high flags).
    if (threadIdx.x < 8) {
        int k = threadIdx.x;
        int lin = ((k >> 2) & 1) * (31 * 1024) + ((k >> 1) & 1) * (31 * 32) + (k & 1) * 31;
        const float* c = cpb + 3 * lin;
        s_corner[k] = make_float4(__ldg(c), __ldg(c + 1), __ldg(c + 2), __ldg(vb + lin));
    }
    // Stage the batch's points once (shared across all 3 symmetries).
    for (int i = threadIdx.x; i < N_PTS; i += NTHREADS)
        s_pts[i] = make_float4(pb[3 * i + 0], pb[3 * i + 1], pb[3 * i + 2], 0.0f);
    __syncthreads();

    // Hoist all symmetry params into registers.
    float plx[S_SYM], ply[S_SYM], plz[S_SYM], plw[S_SYM], inv[S_SYM];
    float qw[S_SYM], qx[S_SYM], qy[S_SYM], qz[S_SYM];
    #pragma unroll
    for (int s = 0; s < S_SYM; s++) {
        float4 pl = reinterpret_cast<const float4*>(planes)[s * B_BATCH + b];
        float4 qq = reinterpret_cast<const float4*>(quats)[s * B_BATCH + b];
        plx[s] = pl.x; ply[s] = pl.y; plz[s] = pl.z; plw[s] = pl.w;
        inv[s] = fast_rcp(pl.x * pl.x + pl.y * pl.y + pl.z * pl.z + 1e-8f);
        qw[s] = qq.x; qx[s] = qq.y; qy[s] = qq.z; qz[s] = qq.w;
    }

    float lp = 0.0f, lq = 0.0f;

    for (int n = threadIdx.x; n < N_PTS; n += NTHREADS) {
        float4 p = s_pts[n];
        const float px = p.x, py = p.y, pz = p.z;

        float tx[6], ty[6], tz[6];
        int lin[6];
        bool crn[6];
        int ck[6];
        #pragma unroll
        for (int s = 0; s < S_SYM; s++) {
            // plane reflection
            float t = 2.0f * (px * plx[s] + py * ply[s] + pz * plz[s] + plw[s]) * inv[s];
            tx[2 * s] = px - t * plx[s];
            ty[2 * s] = py - t * ply[s];
            tz[2 * s] = pz - t * plz[s];
            // quat rotation
            float tw = -qx[s] * px - qy[s] * py - qz[s] * pz;
            float ax =  qw[s] * px + qy[s] * pz - qz[s] * py;
            float ay =  qw[s] * py - qx[s] * pz + qz[s] * px;
            float az =  qw[s] * pz + qx[s] * py - qy[s] * px;
            tx[2 * s + 1] = -tw * qx[s] + ax * qw[s] - ay * qz[s] + az * qy[s];
            ty[2 * s + 1] = -tw * qy[s] + ax * qz[s] + ay * qw[s] - az * qx[s];
            tz[2 * s + 1] = -tw * qz[s] - ax * qy[s] + ay * qx[s] + az * qw[s];
        }
        #pragma unroll
        for (int j = 0; j < 6; j++) {
            // vx = round(clip((p-GRID_MIN)*32, 0, 31)), round-half-even == jnp.round
            float vx = fminf(fmaxf((tx[j] - GRID_MIN_F) * 32.0f, 0.0f), 31.0f);
            float vy = fminf(fmaxf((ty[j] - GRID_MIN_F) * 32.0f, 0.0f), 31.0f);
            float vz = fminf(fmaxf((tz[j] - GRID_MIN_F) * 32.0f, 0.0f), 31.0f);
            int ix = __float2int_rn(vx);
            int iy = __float2int_rn(vy);
            int iz = __float2int_rn(vz);
            lin[j] = ix * 1024 + iy * 32 + iz;
            // corner iff every coord is 0 or 31
            crn[j] = (ix * (31 - ix) == 0) && (iy * (31 - iy) == 0) && (iz * (31 - iz) == 0);
            ck[j]  = ((ix >> 4) << 2) | ((iy >> 4) << 1) | (iz >> 4);
        }

        // Gather: corners from smem (no LDG), others from global.
        float vm[6], c0[6], c1[6], c2[6];
        #pragma unroll
        for (int j = 0; j < 6; j++) {
            if (crn[j]) {
                float4 cc = s_corner[ck[j]];
                c0[j] = cc.x; c1[j] = cc.y; c2[j] = cc.z; vm[j] = cc.w;
            } else {
                const float* c = cpb + 3 * lin[j];
                vm[j] = __ldg(vb + lin[j]);
                c0[j] = __ldg(c + 0);
                c1[j] = __ldg(c + 1);
                c2[j] = __ldg(c + 2);
            }
        }

        #pragma unroll
        for (int j = 0; j < 6; j++) {
            float m  = 1.0f - vm[j];
            float dx = (tx[j] - c0[j]) * m;
            float dy = (ty[j] - c1[j]) * m;
            float dz = (tz[j] - c2[j]) * m;
            float r  = fast_sqrt(fmaxf(dx * dx + dy * dy + dz * dz, 1e-30f));
            if (j & 1) lq += r; else lp += r;
        }
    }

    // Deterministic block reduction: warp shuffle then fixed-order smem sum.
    #pragma unroll
    for (int off = 16; off > 0; off >>= 1) {
        lp += __shfl_down_sync(0xffffffffu, lp, off);
        lq += __shfl_down_sync(0xffffffffu, lq, off);
    }
    const int lane = threadIdx.x & 31;
    const int wid  = threadIdx.x >> 5;
    if (lane == 0) { s_red[wid] = lp; s_red[NWARPS + wid] = lq; }
    __syncthreads();
    if (threadIdx.x == 0) {
        float a = 0.0f, c2s = 0.0f;
        #pragma unroll
        for (int i = 0; i < NWARPS; i++) { a += s_red[i]; c2s += s_red[NWARPS + i]; }
        g_partial[b] = a;
        g_partial[B_BATCH + b] = c2s;
        __threadfence();
        unsigned t = atomicAdd(&g_count, 1u);
        s_is_last = (t == B_BATCH - 1);
    }
    __syncthreads();

    // Last block performs the final reduction in a FIXED order (deterministic
    // regardless of which block finishes last).
    if (s_is_last) {
        float a = 0.0f, c2s = 0.0f;
        for (int i = threadIdx.x; i < B_BATCH; i += NTHREADS) {
            a   += g_partial[i];
            c2s += g_partial[B_BATCH + i];
        }
        #pragma unroll
        for (int off = 16; off > 0; off >>= 1) {
            a   += __shfl_down_sync(0xffffffffu, a,   off);
            c2s += __shfl_down_sync(0xffffffffu, c2s, off);
        }
        if (lane == 0) { s_red[wid] = a; s_red[NWARPS + wid] = c2s; }
        __syncthreads();
        if (threadIdx.x == 0) {
            float sa = 0.0f, sc = 0.0f;
            #pragma unroll
            for (int i = 0; i < NWARPS; i++) { sa += s_red[i]; sc += s_red[NWARPS + i]; }
            out[0] = sa * (1.0f / (float)SB_TOT);
            out[1] = sc * (1.0f / (float)SB_TOT);
            g_count = 0;   // reset for next graph replay
        }
    }
}

extern "C" void kernel_launch(void* const* d_in, const int* in_sizes, int n_in,
                              void* d_out, int out_size)
{
    const float* planes = (const float*)d_in[0];  // (3,512,4)
    const float* quats  = (const float*)d_in[1];  // (3,512,4)
    const float* cps    = (const float*)d_in[2];  // (512, 32768*3)
    const float* pts    = (const float*)d_in[3];  // (512,1000,3)
    const float* vol    = (const float*)d_in[4];  // (512,1,32,32,32)
    float* out = (float*)d_out;                   // [lp_mean, lq_mean]

    sym_loss_kernel<<<B_BATCH, NTHREADS>>>(planes, quats, cps, pts, vol, out);
}